// round 3
// baseline (speedup 1.0000x reference)
#include <cuda_runtime.h>
#include <cstdint>

#define TT   512
#define BB   128
#define NIN  256
#define NH   1024
#define NOUT 32

// ---------------- device scratch ----------------
__device__ unsigned int g_idx[TT * BB * 64];      // per (t,b): up to 256 uint8 indices
__device__ int          g_cnt[TT * BB];
__device__ unsigned int g_zbits[TT * BB * 32];    // hidden spike bitmask (even/odd permuted)
__device__ float        g_whT[NIN * NH];          // w_h transposed [i][h]
__device__ float        g_woT[NH * NOUT];         // w_o transposed [h][o]
__device__ float        g_co[TT * BB * NOUT];     // output currents
__device__ int          g_ctr[16];                // per-htile work counters

#define ADD2(acc, val) asm("add.rn.f32x2 %0, %1, %2;" : "=l"(acc) : "l"(acc), "l"(val))

// ---------------- reset work counters (graph-replay determinism) ----------------
__global__ void reset_kernel() {
    if (threadIdx.x < 16) g_ctr[threadIdx.x] = 0;
}

// ---------------- transposes ----------------
__global__ void transpose_wh_kernel(const float* __restrict__ w_h) {
    int k = blockIdx.x * blockDim.x + threadIdx.x;
    if (k < NH * NIN) {
        int h = k >> 8;
        int i = k & 255;
        g_whT[i * NH + h] = w_h[k];
    }
}

__global__ void transpose_wo_kernel(const float* __restrict__ w_o) {
    int k = blockIdx.x * blockDim.x + threadIdx.x;
    if (k < NOUT * NH) {
        int o = k >> 10;
        int h = k & 1023;
        g_woT[h * NOUT + o] = w_o[k];
    }
}

// ---------------- compact input spikes into index lists ----------------
__global__ __launch_bounds__(256) void compact_kernel(const float* __restrict__ spikes) {
    int tb  = blockIdx.x;
    int tid = threadIdx.x;
    float s = spikes[(size_t)tb * NIN + tid];
    bool p  = (s != 0.0f);
    unsigned m = __ballot_sync(0xffffffffu, p);

    __shared__ int wcnt[8];
    int warp = tid >> 5, lane = tid & 31;
    if (lane == 0) wcnt[warp] = __popc(m);
    __syncthreads();

    int base = 0;
#pragma unroll
    for (int w = 0; w < 8; w++) base += (w < warp) ? wcnt[w] : 0;

    if (p) {
        int pos = base + __popc(m & ((1u << lane) - 1u));
        ((unsigned char*)g_idx)[(size_t)tb * 256 + pos] = (unsigned char)tid;
    }
    if (tid == 0) {
        int tot = 0;
#pragma unroll
        for (int w = 0; w < 8; w++) tot += wcnt[w];
        g_cnt[tb] = tot;
    }
}

// ---------------- fused sparse projection + CUBA LIF scan ----------------
// Persistent: 448 CTAs (28 per h-tile), 256 threads (8 warps). Warp claims one
// batch at a time from its htile's counter -> near-perfect crossbar balance.
// Single f32x2 accumulation chain in index order (bitwise matches R1 numerics).
#define LIF_SMEM (256 * 32 * 8)

__global__ __launch_bounds__(256, 3) void lif_kernel() {
    extern __shared__ unsigned long long s_w2[];   // [i*32 + u] = (w[i][h0+2u], w[i][h0+2u+1])
    int tid   = threadIdx.x;
    int htile = blockIdx.x & 15;
    int h0    = htile << 6;

    for (int k = tid; k < 256 * 32; k += 256) {
        int i = k >> 5, uu = k & 31;
        s_w2[k] = *(const unsigned long long*)(g_whT + i * NH + h0 + 2 * uu);
    }
    __syncthreads();   // only block barrier

    int u = tid & 31;
    const unsigned long long* wrow = s_w2 + u;
    unsigned long long* zout = (unsigned long long*)g_zbits;

    while (true) {
        int b;
        if (u == 0) b = atomicAdd(&g_ctr[htile], 1);
        b = __shfl_sync(0xffffffffu, b, 0);
        if (b >= BB) break;

        size_t tb = (size_t)b;
        uint4 p0 = ((const uint4*)(g_idx + tb * 64))[0];
        uint4 p1 = ((const uint4*)(g_idx + tb * 64))[1];
        int cnt_n = g_cnt[tb];

        float v0 = 0.f, v1 = 0.f, cur0 = 0.f, cur1 = 0.f;

        for (int t = 0; t < TT; t++) {
            uint4 q0 = p0, q1 = p1;
            int cnt = cnt_n;
            size_t tbn = tb + BB;
            if (t + 1 < TT) {
                p0 = ((const uint4*)(g_idx + tbn * 64))[0];
                p1 = ((const uint4*)(g_idx + tbn * 64))[1];
                cnt_n = g_cnt[tbn];
            }

            unsigned w8[8] = {q0.x, q0.y, q0.z, q0.w, q1.x, q1.y, q1.z, q1.w};
            int nw = cnt >> 2;

            unsigned long long acc = 0ull;   // single chain, exact index order
#pragma unroll
            for (int kw = 0; kw < 8; kw++) {
                if (kw >= nw) break;
                unsigned wd = w8[kw];
                ADD2(acc, wrow[(wd & 255u) << 5]);
                ADD2(acc, wrow[((wd >> 8) & 255u) << 5]);
                ADD2(acc, wrow[((wd >> 16) & 255u) << 5]);
                ADD2(acc, wrow[(wd >> 24) << 5]);
            }
            for (int kw = 8; kw < nw; kw++) {   // rare tail (>32 actives)
                unsigned wd = g_idx[tb * 64 + kw];
                ADD2(acc, wrow[(wd & 255u) << 5]);
                ADD2(acc, wrow[((wd >> 8) & 255u) << 5]);
                ADD2(acc, wrow[((wd >> 16) & 255u) << 5]);
                ADD2(acc, wrow[(wd >> 24) << 5]);
            }
            int rem = cnt & 3;
            if (rem) {
                unsigned wd;
                if (nw >= 8) {
                    wd = g_idx[tb * 64 + nw];
                } else {
                    wd = w8[0];
#pragma unroll
                    for (int k = 1; k < 8; k++) if (nw == k) wd = w8[k];
                }
                ADD2(acc, wrow[(wd & 255u) << 5]);
                if (rem > 1) ADD2(acc, wrow[((wd >> 8) & 255u) << 5]);
                if (rem > 2) ADD2(acc, wrow[((wd >> 16) & 255u) << 5]);
            }

            float c0, c1;
            asm("mov.b64 {%0, %1}, %2;" : "=f"(c0), "=f"(c1) : "l"(acc));

            // CUBA LIF (exact fp32)
            cur0 = cur0 * 0.875f + c0;
            v0   = v0 + 0.125f * (cur0 - v0);
            bool z0 = (v0 - 1.0f) > 0.0f;
            if (z0) v0 = 0.0f;

            cur1 = cur1 * 0.875f + c1;
            v1   = v1 + 0.125f * (cur1 - v1);
            bool z1 = (v1 - 1.0f) > 0.0f;
            if (z1) v1 = 0.0f;

            unsigned mE = __ballot_sync(0xffffffffu, z0);
            unsigned mO = __ballot_sync(0xffffffffu, z1);
            if (u == 0)
                zout[tb * 16 + htile] = (unsigned long long)mE | ((unsigned long long)mO << 32);

            tb = tbn;
        }
    }
}

// ---------------- output currents: smem-free LDG gather (w_oT is L1-resident) ----------------
// 2048 blocks x 256 threads = 16384 warps; warp handles 4 (t,b) units.
__global__ __launch_bounds__(256) void cout_kernel() {
    int gw   = (blockIdx.x * blockDim.x + threadIdx.x) >> 5;   // 0..16383
    int lane = threadIdx.x & 31;

#pragma unroll
    for (int k = 0; k < 4; k++) {
        int unit = gw + 16384 * k;    // = t*BB + b
        unsigned m = __ldcs(&g_zbits[(size_t)unit * 32 + lane]);
        float c0 = 0.f, c1 = 0.f;
#pragma unroll
        for (int wi = 0; wi < 32; wi++) {
            unsigned mw = __shfl_sync(0xffffffffu, m, wi);
            // un-permute: h = (wi>>1)*64 + (wi&1) + 2p
            int base = (((wi >> 1) << 6) + (wi & 1)) * NOUT + lane;
            while (mw) {
                int p = __ffs(mw) - 1; mw &= mw - 1;
                c0 += __ldg(&g_woT[base + (p << 6)]);
                if (mw) {
                    int p2 = __ffs(mw) - 1; mw &= mw - 1;
                    c1 += __ldg(&g_woT[base + (p2 << 6)]);
                }
            }
        }
        __stcs(&g_co[(size_t)unit * 32 + lane], c0 + c1);
    }
}

// ---------------- CUBA LI readout with 8-deep prefetch ----------------
__global__ __launch_bounds__(256) void li_kernel(float* __restrict__ out) {
    int gid = blockIdx.x * blockDim.x + threadIdx.x;  // 0..4095
    float v = 0.f, cur = 0.f;
    float cb[8], cn[8];
#pragma unroll
    for (int j = 0; j < 8; j++) cb[j] = g_co[(size_t)j * (BB * NOUT) + gid];

    for (int tb = 0; tb < TT; tb += 8) {
        if (tb + 8 < TT) {
#pragma unroll
            for (int j = 0; j < 8; j++)
                cn[j] = g_co[(size_t)(tb + 8 + j) * (BB * NOUT) + gid];
        }
#pragma unroll
        for (int j = 0; j < 8; j++) {
            cur = cur * 0.875f + cb[j];
            v = v + 0.125f * (cur - v);
            out[(size_t)(tb + j) * (BB * NOUT) + gid] = v;
        }
#pragma unroll
        for (int j = 0; j < 8; j++) cb[j] = cn[j];
    }
}

// ---------------- launch ----------------
extern "C" void kernel_launch(void* const* d_in, const int* in_sizes, int n_in,
                              void* d_out, int out_size) {
    const float* spikes = (const float*)d_in[0];   // [512,128,256]
    const float* w_h    = (const float*)d_in[1];   // [1024,256]
    const float* w_o    = (const float*)d_in[2];   // [32,1024]
    float* out = (float*)d_out;                    // [512,128,32]

    cudaFuncSetAttribute(lif_kernel, cudaFuncAttributeMaxDynamicSharedMemorySize, LIF_SMEM);

    reset_kernel<<<1, 32>>>();
    transpose_wh_kernel<<<(NH * NIN + 1023) / 1024, 1024>>>(w_h);
    transpose_wo_kernel<<<(NOUT * NH + 255) / 256, 256>>>(w_o);
    compact_kernel<<<TT * BB, 256>>>(spikes);
    lif_kernel<<<448, 256, LIF_SMEM>>>();
    cout_kernel<<<2048, 256>>>();
    li_kernel<<<16, 256>>>(out);
}